// round 1
// baseline (speedup 1.0000x reference)
#include <cuda_runtime.h>

// Problem constants
#define EE 2048
#define HH 3
#define BB 4
#define NN 2048

// Scratch buffers (no cudaMalloc allowed)
__device__ float g_Q[(size_t)HH * BB * NN * EE];
__device__ float g_K[(size_t)HH * BB * NN * EE];
__device__ float g_V[(size_t)HH * BB * NN * EE];
__device__ float g_S[(size_t)HH * BB * NN * NN];
__device__ float g_M[(size_t)BB * NN * EE];

#define TM 128
#define TN 128
#define TK 16

// ---------------------------------------------------------------------------
// NT GEMM: C[m,n] = alpha * sum_k A[m,k] * B[n,k]  (+ bias[n] if bias != 0)
// A: [M,K] row-major, B: [N,K] row-major. All dims multiples of 128/16.
// blockIdx.z selects batch slice via strides sA/sB/sC.
// ---------------------------------------------------------------------------
__global__ void __launch_bounds__(256, 2) gemm_nt_kernel(
    const float* __restrict__ Ab, const float* __restrict__ Bbp,
    float* __restrict__ Cb, const float* __restrict__ bias,
    int M, int Ncols, int K, float alpha,
    long long sA, long long sB, long long sC)
{
    const float* A = Ab + (long long)blockIdx.z * sA;
    const float* B = Bbp + (long long)blockIdx.z * sB;
    float* C       = Cb + (long long)blockIdx.z * sC;

    __shared__ float As[TK][TM + 4];
    __shared__ float Bs[TK][TN + 4];

    const int tid = threadIdx.x;
    const int m0 = blockIdx.y * TM;
    const int n0 = blockIdx.x * TN;
    const int tx = tid & 15;   // 0..15  (column group)
    const int ty = tid >> 4;   // 0..15  (row group)

    float acc[8][8];
#pragma unroll
    for (int i = 0; i < 8; i++)
#pragma unroll
        for (int j = 0; j < 8; j++) acc[i][j] = 0.f;

    for (int k0 = 0; k0 < K; k0 += TK) {
        // Load A tile (TM rows x TK) transposed into As[k][m]
#pragma unroll
        for (int it = 0; it < 2; it++) {
            int i = tid + it * 256;        // 0..511
            int row = i >> 2;
            int kq = (i & 3) << 2;
            float4 v = *(const float4*)(A + (long long)(m0 + row) * K + k0 + kq);
            As[kq + 0][row] = v.x; As[kq + 1][row] = v.y;
            As[kq + 2][row] = v.z; As[kq + 3][row] = v.w;
        }
        // Load B tile (TN rows x TK) transposed into Bs[k][n]
#pragma unroll
        for (int it = 0; it < 2; it++) {
            int i = tid + it * 256;
            int row = i >> 2;
            int kq = (i & 3) << 2;
            float4 v = *(const float4*)(B + (long long)(n0 + row) * K + k0 + kq);
            Bs[kq + 0][row] = v.x; Bs[kq + 1][row] = v.y;
            Bs[kq + 2][row] = v.z; Bs[kq + 3][row] = v.w;
        }
        __syncthreads();

#pragma unroll
        for (int k = 0; k < TK; k++) {
            float4 a0 = *(const float4*)&As[k][ty * 8];
            float4 a1 = *(const float4*)&As[k][ty * 8 + 4];
            float4 b0 = *(const float4*)&Bs[k][tx * 8];
            float4 b1 = *(const float4*)&Bs[k][tx * 8 + 4];
            float a[8] = {a0.x, a0.y, a0.z, a0.w, a1.x, a1.y, a1.z, a1.w};
            float b[8] = {b0.x, b0.y, b0.z, b0.w, b1.x, b1.y, b1.z, b1.w};
#pragma unroll
            for (int i = 0; i < 8; i++)
#pragma unroll
                for (int j = 0; j < 8; j++)
                    acc[i][j] += a[i] * b[j];
        }
        __syncthreads();
    }

#pragma unroll
    for (int i = 0; i < 8; i++) {
        int m = m0 + ty * 8 + i;
#pragma unroll
        for (int j = 0; j < 8; j += 4) {
            int n = n0 + tx * 8 + j;
            float4 v;
            v.x = acc[i][j + 0] * alpha;
            v.y = acc[i][j + 1] * alpha;
            v.z = acc[i][j + 2] * alpha;
            v.w = acc[i][j + 3] * alpha;
            if (bias) {
                v.x += bias[n + 0]; v.y += bias[n + 1];
                v.z += bias[n + 2]; v.w += bias[n + 3];
            }
            *(float4*)(C + (long long)m * Ncols + n) = v;
        }
    }
}

// ---------------------------------------------------------------------------
// Softmax over the QUERY axis: S[hb][n][m], normalize along n for each m.
// One thread per key-column m -> fully coalesced strided passes.
// ---------------------------------------------------------------------------
__global__ void softmax_query_kernel(float* __restrict__ Sg)
{
    float* s = Sg + (long long)blockIdx.y * NN * NN;
    int m = blockIdx.x * blockDim.x + threadIdx.x;

    float mx = -1e30f;
    for (int n = 0; n < NN; n++)
        mx = fmaxf(mx, s[(long long)n * NN + m]);
    float sum = 0.f;
    for (int n = 0; n < NN; n++)
        sum += __expf(s[(long long)n * NN + m] - mx);
    float inv = 1.f / sum;
    for (int n = 0; n < NN; n++) {
        long long idx = (long long)n * NN + m;
        s[idx] = __expf(s[idx] - mx) * inv;
    }
}

// ---------------------------------------------------------------------------
// attn + head-mean (NN GEMM, head loop folded in):
//   C[b][n][d] = (1/3) * sum_h sum_m W[h,b,n,m] * V[h,b,m,d]
// A is k-contiguous (like NT A), B (=V) is n-contiguous (NN form).
// blockIdx.z = b.
// ---------------------------------------------------------------------------
__global__ void __launch_bounds__(256, 2) attn_mean_kernel(
    const float* __restrict__ Wg, const float* __restrict__ Vg,
    float* __restrict__ Cg)
{
    const int b = blockIdx.z;
    __shared__ float As[TK][TM + 4];
    __shared__ float Bs[TK][TN + 4];

    const int tid = threadIdx.x;
    const int m0 = blockIdx.y * TM;   // query rows n
    const int n0 = blockIdx.x * TN;   // output cols d
    const int tx = tid & 15;
    const int ty = tid >> 4;

    float acc[8][8];
#pragma unroll
    for (int i = 0; i < 8; i++)
#pragma unroll
        for (int j = 0; j < 8; j++) acc[i][j] = 0.f;

    for (int h = 0; h < HH; h++) {
        const float* A = Wg + ((long long)h * BB + b) * (long long)NN * NN;
        const float* B = Vg + ((long long)h * BB + b) * (long long)NN * EE;

        for (int k0 = 0; k0 < NN; k0 += TK) {
            // A tile: rows of W (k-contiguous), store transposed As[k][m]
#pragma unroll
            for (int it = 0; it < 2; it++) {
                int i = tid + it * 256;
                int row = i >> 2;
                int kq = (i & 3) << 2;
                float4 v = *(const float4*)(A + (long long)(m0 + row) * NN + k0 + kq);
                As[kq + 0][row] = v.x; As[kq + 1][row] = v.y;
                As[kq + 2][row] = v.z; As[kq + 3][row] = v.w;
            }
            // B tile: V rows are d-contiguous -> direct Bs[k][n] load
#pragma unroll
            for (int it = 0; it < 2; it++) {
                int i = tid + it * 256;      // 0..511, 16 rows x 32 float4
                int row = i >> 5;            // 0..15
                int c4 = (i & 31) << 2;      // 0..124
                float4 v = *(const float4*)(B + (long long)(k0 + row) * EE + n0 + c4);
                *(float4*)&Bs[row][c4] = v;
            }
            __syncthreads();

#pragma unroll
            for (int k = 0; k < TK; k++) {
                float4 a0 = *(const float4*)&As[k][ty * 8];
                float4 a1 = *(const float4*)&As[k][ty * 8 + 4];
                float4 b0 = *(const float4*)&Bs[k][tx * 8];
                float4 b1 = *(const float4*)&Bs[k][tx * 8 + 4];
                float a[8] = {a0.x, a0.y, a0.z, a0.w, a1.x, a1.y, a1.z, a1.w};
                float bb[8] = {b0.x, b0.y, b0.z, b0.w, b1.x, b1.y, b1.z, b1.w};
#pragma unroll
                for (int i = 0; i < 8; i++)
#pragma unroll
                    for (int j = 0; j < 8; j++)
                        acc[i][j] += a[i] * bb[j];
            }
            __syncthreads();
        }
    }

    const float inv3 = 1.0f / 3.0f;
    float* C = Cg + (long long)b * NN * EE;
#pragma unroll
    for (int i = 0; i < 8; i++) {
        int m = m0 + ty * 8 + i;
#pragma unroll
        for (int j = 0; j < 8; j += 4) {
            int n = n0 + tx * 8 + j;
            float4 v;
            v.x = acc[i][j + 0] * inv3;
            v.y = acc[i][j + 1] * inv3;
            v.z = acc[i][j + 2] * inv3;
            v.w = acc[i][j + 3] * inv3;
            *(float4*)(C + (long long)m * EE + n) = v;
        }
    }
}

// ---------------------------------------------------------------------------
extern "C" void kernel_launch(void* const* d_in, const int* in_sizes, int n_in,
                              void* d_out, int out_size)
{
    const float* x    = (const float*)d_in[0];   // [B,N,E]
    const float* Wq   = (const float*)d_in[1];   // [H,E,E]
    const float* Wk   = (const float*)d_in[2];
    const float* Wv   = (const float*)d_in[3];
    const float* fc_w = (const float*)d_in[4];   // [E,E]
    const float* fc_b = (const float*)d_in[5];   // [E]
    float* out = (float*)d_out;                  // [B,N,E]

    float* Q = nullptr; float* K = nullptr; float* V = nullptr;
    float* S = nullptr; float* Mn = nullptr;
    cudaGetSymbolAddress((void**)&Q,  g_Q);
    cudaGetSymbolAddress((void**)&K,  g_K);
    cudaGetSymbolAddress((void**)&V,  g_V);
    cudaGetSymbolAddress((void**)&S,  g_S);
    cudaGetSymbolAddress((void**)&Mn, g_M);

    const int Mrows = BB * NN;                  // 8192
    const long long sW = (long long)EE * EE;    // per-head weight stride
    const long long sQKV = (long long)BB * NN * EE;  // per-head Q/K/V stride

    // 1) Projections: Q/K/V[h] = X @ W[h]^T  (z = head)
    {
        dim3 grid(EE / TN, Mrows / TM, HH);
        gemm_nt_kernel<<<grid, 256>>>(x, Wq, Q, nullptr, Mrows, EE, EE, 1.0f, 0, sW, sQKV);
        gemm_nt_kernel<<<grid, 256>>>(x, Wk, K, nullptr, Mrows, EE, EE, 1.0f, 0, sW, sQKV);
        gemm_nt_kernel<<<grid, 256>>>(x, Wv, V, nullptr, Mrows, EE, EE, 1.0f, 0, sW, sQKV);
    }

    // 2) scores[hb] = Q[hb] @ K[hb]^T * (1/sqrt(E))  (z = h*B+b)
    {
        dim3 grid(NN / TN, NN / TM, HH * BB);
        const float scale = 1.0f / sqrtf((float)EE);
        gemm_nt_kernel<<<grid, 256>>>(Q, K, S, nullptr, NN, NN, EE, scale,
                                      (long long)NN * EE, (long long)NN * EE,
                                      (long long)NN * NN);
    }

    // 3) softmax over the query axis (in-place)
    {
        dim3 grid(NN / 256, HH * BB);
        softmax_query_kernel<<<grid, 256>>>(S);
    }

    // 4) attn + mean over heads
    {
        dim3 grid(EE / TN, NN / TM, BB);
        attn_mean_kernel<<<grid, 256>>>(S, V, Mn);
    }

    // 5) out = mean @ fc_w^T + fc_b
    {
        dim3 grid(EE / TN, Mrows / TM, 1);
        gemm_nt_kernel<<<grid, 256>>>(Mn, fc_w, out, fc_b, Mrows, EE, EE, 1.0f, 0, 0, 0);
    }
}

// round 14
// speedup vs baseline: 1.9558x; 1.9558x over previous
#include <cuda_runtime.h>
#include <cstdint>

#define EE  2048
#define HH  3
#define BB  4
#define SEQ 2048

// Scratch (no cudaMalloc allowed)
__device__ float g_Q[(size_t)HH * BB * SEQ * EE];
__device__ float g_K[(size_t)HH * BB * SEQ * EE];
__device__ float g_V[(size_t)HH * BB * SEQ * EE];
__device__ float g_S[(size_t)HH * BB * SEQ * SEQ];
__device__ float g_M[(size_t)BB * SEQ * EE];

__device__ __forceinline__ uint32_t f2tf32(float f) {
    uint32_t r;
    asm("cvt.rna.tf32.f32 %0, %1;" : "=r"(r) : "f"(f));
    return r;
}

__device__ __forceinline__ void mma_tf32(
    float& c0, float& c1, float& c2, float& c3,
    uint32_t a0, uint32_t a1, uint32_t a2, uint32_t a3,
    uint32_t b0, uint32_t b1)
{
    asm volatile(
        "mma.sync.aligned.m16n8k8.row.col.f32.tf32.tf32.f32 "
        "{%0,%1,%2,%3}, {%4,%5,%6,%7}, {%8,%9}, {%0,%1,%2,%3};"
        : "+f"(c0), "+f"(c1), "+f"(c2), "+f"(c3)
        : "r"(a0), "r"(a1), "r"(a2), "r"(a3), "r"(b0), "r"(b1));
}

// ---------------------------------------------------------------------------
// HMMA tf32 GEMM: C[m,n] = alpha * sum_acc sum_k A[m,k] * Bop[n,k] (+ bias[n])
//   A: [M,K] row-major (lda=K); batched by blockIdx.z (sA/sB/sC) and acc loop
//   transB=0: B is [N,K] row-major (NT), ldb = row stride
//   transB=1: B is [K,N] row-major (NN), ldb = row stride
// CTA tile 128x128, K-chunk 32. 8 warps (2x4), warp tile 64x32 (4x4 m16n8k8).
// ---------------------------------------------------------------------------
#define PITCH 132

__global__ void __launch_bounds__(256, 2) gemm_mma(
    const float* __restrict__ Ag, const float* __restrict__ Bg,
    float* __restrict__ Cg, const float* __restrict__ bias,
    int M, int Ncols, int K, int ldb, float alpha,
    long long sA, long long sB, long long sC,
    int nacc, long long aA, long long aB, int transB)
{
    __shared__ uint32_t As[32][PITCH];
    __shared__ uint32_t Bs[32][PITCH];

    const int tid = threadIdx.x;
    const int warp = tid >> 5, lane = tid & 31;
    const int g = lane >> 2, c = lane & 3;          // groupID / threadID_in_group

    const long long z = blockIdx.z;
    const float* Ab = Ag + z * sA;
    const float* Bb = Bg + z * sB;
    float* C = Cg + z * sC;
    const int m0 = blockIdx.y * 128, n0 = blockIdx.x * 128;

    const int ma = (warp & 1) * 64;                 // warp m-offset in tile
    const int na = (warp >> 1) * 32;                // warp n-offset in tile

    float acc[4][4][4];
#pragma unroll
    for (int i = 0; i < 4; i++)
#pragma unroll
        for (int j = 0; j < 4; j++)
#pragma unroll
            for (int r = 0; r < 4; r++) acc[i][j][r] = 0.f;

    const int nK = K >> 5;
    const int L = nacc * nK;

    for (int it = 0; it < L; ++it) {
        const int accb = it / nK;
        const int k0 = (it - accb * nK) << 5;
        const float* A = Ab + (long long)accb * aA;
        const float* B = Bb + (long long)accb * aB;

        // ---- stage A: 128 rows x 32 k, transposed -> As[k][m], tf32-rounded
#pragma unroll
        for (int i2 = 0; i2 < 4; i2++) {
            int idx = tid + i2 * 256;               // 0..1023
            int row = idx >> 3, kq = (idx & 7) << 2;
            float4 v = *(const float4*)(A + (long long)(m0 + row) * K + k0 + kq);
            As[kq + 0][row] = f2tf32(v.x);
            As[kq + 1][row] = f2tf32(v.y);
            As[kq + 2][row] = f2tf32(v.z);
            As[kq + 3][row] = f2tf32(v.w);
        }
        // ---- stage B -> Bs[k][n]
        if (!transB) {
#pragma unroll
            for (int i2 = 0; i2 < 4; i2++) {
                int idx = tid + i2 * 256;           // 0..1023
                int row = idx >> 3, kq = (idx & 7) << 2;
                float4 v = *(const float4*)(B + (long long)(n0 + row) * ldb + k0 + kq);
                Bs[kq + 0][row] = f2tf32(v.x);
                Bs[kq + 1][row] = f2tf32(v.y);
                Bs[kq + 2][row] = f2tf32(v.z);
                Bs[kq + 3][row] = f2tf32(v.w);
            }
        } else {
#pragma unroll
            for (int i2 = 0; i2 < 4; i2++) {
                int idx = tid + i2 * 256;           // 32 k x 32 n-quads
                int kk = idx >> 5, q = idx & 31;
                float4 v = *(const float4*)(B + (long long)(k0 + kk) * ldb + n0 + q * 4);
                uint4 u;
                u.x = f2tf32(v.x); u.y = f2tf32(v.y);
                u.z = f2tf32(v.z); u.w = f2tf32(v.w);
                *(uint4*)&Bs[kk][q * 4] = u;
            }
        }
        __syncthreads();

        // ---- compute: 4 k8 steps, 16 mmas each
#pragma unroll
        for (int kb8 = 0; kb8 < 4; kb8++) {
            const int kb = kb8 * 8;
            uint32_t a[4][4], b[4][2];
#pragma unroll
            for (int mt = 0; mt < 4; mt++) {
                int m = ma + mt * 16 + g;
                a[mt][0] = As[kb + c][m];
                a[mt][1] = As[kb + c][m + 8];
                a[mt][2] = As[kb + c + 4][m];
                a[mt][3] = As[kb + c + 4][m + 8];
            }
#pragma unroll
            for (int nt = 0; nt < 4; nt++) {
                int n = na + nt * 8 + g;
                b[nt][0] = Bs[kb + c][n];
                b[nt][1] = Bs[kb + c + 4][n];
            }
#pragma unroll
            for (int mt = 0; mt < 4; mt++)
#pragma unroll
                for (int nt = 0; nt < 4; nt++)
                    mma_tf32(acc[mt][nt][0], acc[mt][nt][1], acc[mt][nt][2], acc[mt][nt][3],
                             a[mt][0], a[mt][1], a[mt][2], a[mt][3],
                             b[nt][0], b[nt][1]);
        }
        __syncthreads();
    }

    // ---- epilogue: c0:(g,2c) c1:(g,2c+1) c2:(g+8,2c) c3:(g+8,2c+1)
#pragma unroll
    for (int nt = 0; nt < 4; nt++) {
        int col = n0 + na + nt * 8 + 2 * c;
        float bv0 = bias ? bias[col] : 0.f;
        float bv1 = bias ? bias[col + 1] : 0.f;
#pragma unroll
        for (int mt = 0; mt < 4; mt++) {
            int row = m0 + ma + mt * 16 + g;
            float2 v0, v1;
            v0.x = acc[mt][nt][0] * alpha + bv0;
            v0.y = acc[mt][nt][1] * alpha + bv1;
            v1.x = acc[mt][nt][2] * alpha + bv0;
            v1.y = acc[mt][nt][3] * alpha + bv1;
            *(float2*)(C + (long long)row * Ncols + col) = v0;
            *(float2*)(C + (long long)(row + 8) * Ncols + col) = v1;
        }
    }
}

// ---------------- softmax over the QUERY axis ----------------
__global__ void softmax_query_kernel(float* __restrict__ Sg)
{
    float* s = Sg + (long long)blockIdx.y * SEQ * SEQ;
    int m = blockIdx.x * blockDim.x + threadIdx.x;

    float mx = -1e30f;
    for (int n = 0; n < SEQ; n++) mx = fmaxf(mx, s[(long long)n * SEQ + m]);
    float sum = 0.f;
    for (int n = 0; n < SEQ; n++) {
        long long idx = (long long)n * SEQ + m;
        float e = __expf(s[idx] - mx);
        s[idx] = e;
        sum += e;
    }
    float inv = 1.f / sum;
    for (int n = 0; n < SEQ; n++) s[(long long)n * SEQ + m] *= inv;
}

// ---------------------------------------------------------------------------
extern "C" void kernel_launch(void* const* d_in, const int* in_sizes, int n_in,
                              void* d_out, int out_size)
{
    const float* x    = (const float*)d_in[0];   // [B,N,E]
    const float* Wq   = (const float*)d_in[1];   // [H,E,E]
    const float* Wk   = (const float*)d_in[2];
    const float* Wv   = (const float*)d_in[3];
    const float* fc_w = (const float*)d_in[4];   // [E,E]
    const float* fc_b = (const float*)d_in[5];   // [E]
    float* out = (float*)d_out;                  // [B,N,E]

    float *Q, *K, *V, *S, *Mn;
    cudaGetSymbolAddress((void**)&Q,  g_Q);
    cudaGetSymbolAddress((void**)&K,  g_K);
    cudaGetSymbolAddress((void**)&V,  g_V);
    cudaGetSymbolAddress((void**)&S,  g_S);
    cudaGetSymbolAddress((void**)&Mn, g_M);

    const int Mrows = BB * SEQ;                        // 8192
    const long long sW   = (long long)EE * EE;
    const long long sQKV = (long long)BB * SEQ * EE;

    // 1) Q/K/V[h] = X @ W[h]^T   (z = head)
    {
        dim3 grid(EE / 128, Mrows / 128, HH);
        gemm_mma<<<grid, 256>>>(x, Wq, Q, nullptr, Mrows, EE, EE, EE, 1.0f,
                                0, sW, sQKV, 1, 0, 0, 0);
        gemm_mma<<<grid, 256>>>(x, Wk, K, nullptr, Mrows, EE, EE, EE, 1.0f,
                                0, sW, sQKV, 1, 0, 0, 0);
        gemm_mma<<<grid, 256>>>(x, Wv, V, nullptr, Mrows, EE, EE, EE, 1.0f,
                                0, sW, sQKV, 1, 0, 0, 0);
    }

    // 2) S[hb] = Q[hb] @ K[hb]^T * scale   (z = h*B + b)
    {
        dim3 grid(SEQ / 128, SEQ / 128, HH * BB);
        const float scale = 1.0f / sqrtf((float)EE);
        gemm_mma<<<grid, 256>>>(Q, K, S, nullptr, SEQ, SEQ, EE, EE, scale,
                                (long long)SEQ * EE, (long long)SEQ * EE,
                                (long long)SEQ * SEQ, 1, 0, 0, 0);
    }

    // 3) softmax over the query axis (in-place)
    {
        dim3 grid(SEQ / 256, HH * BB);
        softmax_query_kernel<<<grid, 256>>>(S);
    }

    // 4) attn + mean over heads: C[b] = (1/3) * sum_h S[h,b] @ V[h,b]  (NN, z = b)
    {
        dim3 grid(EE / 128, SEQ / 128, BB);
        gemm_mma<<<grid, 256>>>(S, V, Mn, nullptr, SEQ, EE, SEQ, EE, 1.0f / 3.0f,
                                (long long)SEQ * SEQ, (long long)SEQ * EE,
                                (long long)SEQ * EE,
                                HH, (long long)BB * SEQ * SEQ, (long long)BB * SEQ * EE, 1);
    }

    // 5) out = Mn @ fc_w^T + fc_b
    {
        dim3 grid(EE / 128, Mrows / 128, 1);
        gemm_mma<<<grid, 256>>>(Mn, fc_w, out, fc_b, Mrows, EE, EE, EE, 1.0f,
                                0, 0, 0, 1, 0, 0, 0);
    }
}

// round 17
// speedup vs baseline: 2.5984x; 1.3286x over previous
#include <cuda_runtime.h>
#include <cstdint>

#define EE  2048
#define HH  3
#define BB  4
#define SEQ 2048

// Scratch (no cudaMalloc allowed)
__device__ float g_Q[(size_t)HH * BB * SEQ * EE];
__device__ float g_K[(size_t)HH * BB * SEQ * EE];
__device__ float g_V[(size_t)HH * BB * SEQ * EE];
__device__ float g_S[(size_t)HH * BB * SEQ * SEQ];
__device__ float g_M[(size_t)BB * SEQ * EE];

__device__ __forceinline__ uint32_t f2tf32(float f) {
    uint32_t r;
    asm("cvt.rna.tf32.f32 %0, %1;" : "=r"(r) : "f"(f));
    return r;
}

__device__ __forceinline__ void mma_tf32(
    float& c0, float& c1, float& c2, float& c3,
    uint32_t a0, uint32_t a1, uint32_t a2, uint32_t a3,
    uint32_t b0, uint32_t b1)
{
    asm volatile(
        "mma.sync.aligned.m16n8k8.row.col.f32.tf32.tf32.f32 "
        "{%0,%1,%2,%3}, {%4,%5,%6,%7}, {%8,%9}, {%0,%1,%2,%3};"
        : "+f"(c0), "+f"(c1), "+f"(c2), "+f"(c3)
        : "r"(a0), "r"(a1), "r"(a2), "r"(a3), "r"(b0), "r"(b1));
}

// ---------------------------------------------------------------------------
// HMMA tf32 GEMM: C[m,n] = alpha * sum_acc sum_k A[m,k] * Bop[n,k] (+ bias[n])
// CTA tile 128x128, K-chunk 32. 8 warps (2x4), warp tile 64x32 (4x4 m16n8k8).
// A staged row-major [m][k] pitch 36 (STS.128, conflict-free both directions).
// B NT staged row-major [n][k] pitch 36; B transB staged k-major [k][n] pitch
// 132 (gmem float4 runs along n -> STS.128 conflict-free; frag loads 4c+g).
// ---------------------------------------------------------------------------
#define APITCH 36
#define BTPITCH 132

__global__ void __launch_bounds__(256, 2) gemm_mma(
    const float* __restrict__ Ag, const float* __restrict__ Bg,
    float* __restrict__ Cg, const float* __restrict__ bias,
    int M, int Ncols, int K, int ldb, float alpha,
    long long sA, long long sB, long long sC,
    int nacc, long long aA, long long aB, int transB)
{
    __shared__ __align__(16) uint32_t As[128][APITCH];
    __shared__ __align__(16) uint32_t Bs[4608];   // [n][36] NT  or  [k][132] transB

    const int tid = threadIdx.x;
    const int warp = tid >> 5, lane = tid & 31;
    const int g = lane >> 2, c = lane & 3;          // groupID / threadID_in_group

    const long long z = blockIdx.z;
    const float* Ab = Ag + z * sA;
    const float* Bb = Bg + z * sB;
    float* C = Cg + z * sC;
    const int m0 = blockIdx.y * 128, n0 = blockIdx.x * 128;

    const int ma = (warp & 1) * 64;                 // warp m-offset in tile
    const int na = (warp >> 1) * 32;                // warp n-offset in tile

    // fragment-load strides for B (hoisted; NT: [n][36], transB: [k][132])
    const int sK = transB ? BTPITCH : 1;
    const int sN = transB ? 1 : APITCH;

    float acc[4][4][4];
#pragma unroll
    for (int i = 0; i < 4; i++)
#pragma unroll
        for (int j = 0; j < 4; j++)
#pragma unroll
            for (int r = 0; r < 4; r++) acc[i][j][r] = 0.f;

    const int nK = K >> 5;
    const int L = nacc * nK;

    for (int it = 0; it < L; ++it) {
        const int accb = it / nK;
        const int k0 = (it - accb * nK) << 5;
        const float* A = Ab + (long long)accb * aA;
        const float* B = Bb + (long long)accb * aB;

        // ---- stage A row-major [m][k]: one STS.128 per float4, conflict-free
#pragma unroll
        for (int i2 = 0; i2 < 4; i2++) {
            int idx = tid + i2 * 256;               // 0..1023
            int row = idx >> 3, kq = (idx & 7) << 2;
            float4 v = *(const float4*)(A + (long long)(m0 + row) * K + k0 + kq);
            uint4 u;
            u.x = f2tf32(v.x); u.y = f2tf32(v.y);
            u.z = f2tf32(v.z); u.w = f2tf32(v.w);
            *(uint4*)&As[row][kq] = u;
        }
        // ---- stage B
        if (!transB) {
            // row-major [n][k], STS.128 conflict-free
#pragma unroll
            for (int i2 = 0; i2 < 4; i2++) {
                int idx = tid + i2 * 256;           // 0..1023
                int row = idx >> 3, kq = (idx & 7) << 2;
                float4 v = *(const float4*)(B + (long long)(n0 + row) * ldb + k0 + kq);
                uint4 u;
                u.x = f2tf32(v.x); u.y = f2tf32(v.y);
                u.z = f2tf32(v.z); u.w = f2tf32(v.w);
                *(uint4*)&Bs[row * APITCH + kq] = u;
            }
        } else {
            // k-major [k][n]: gmem float4 runs along n -> contiguous STS.128
#pragma unroll
            for (int i2 = 0; i2 < 4; i2++) {
                int idx = tid + i2 * 256;           // 32 k x 32 n-quads
                int kk = idx >> 5, q = idx & 31;
                float4 v = *(const float4*)(B + (long long)(k0 + kk) * ldb + n0 + q * 4);
                uint4 u;
                u.x = f2tf32(v.x); u.y = f2tf32(v.y);
                u.z = f2tf32(v.z); u.w = f2tf32(v.w);
                *(uint4*)&Bs[kk * BTPITCH + q * 4] = u;
            }
        }
        __syncthreads();

        // ---- compute: 4 k8 steps, 16 mmas each
#pragma unroll
        for (int kb8 = 0; kb8 < 4; kb8++) {
            const int kb = kb8 * 8;
            uint32_t a[4][4], b[4][2];
#pragma unroll
            for (int mt = 0; mt < 4; mt++) {
                int m = ma + mt * 16 + g;
                a[mt][0] = As[m][kb + c];
                a[mt][1] = As[m + 8][kb + c];
                a[mt][2] = As[m][kb + c + 4];
                a[mt][3] = As[m + 8][kb + c + 4];
            }
#pragma unroll
            for (int nt = 0; nt < 4; nt++) {
                int n = na + nt * 8 + g;
                b[nt][0] = Bs[(kb + c) * sK + n * sN];
                b[nt][1] = Bs[(kb + c + 4) * sK + n * sN];
            }
#pragma unroll
            for (int mt = 0; mt < 4; mt++)
#pragma unroll
                for (int nt = 0; nt < 4; nt++)
                    mma_tf32(acc[mt][nt][0], acc[mt][nt][1], acc[mt][nt][2], acc[mt][nt][3],
                             a[mt][0], a[mt][1], a[mt][2], a[mt][3],
                             b[nt][0], b[nt][1]);
        }
        __syncthreads();
    }

    // ---- epilogue: c0:(g,2c) c1:(g,2c+1) c2:(g+8,2c) c3:(g+8,2c+1)
#pragma unroll
    for (int nt = 0; nt < 4; nt++) {
        int col = n0 + na + nt * 8 + 2 * c;
        float bv0 = bias ? bias[col] : 0.f;
        float bv1 = bias ? bias[col + 1] : 0.f;
#pragma unroll
        for (int mt = 0; mt < 4; mt++) {
            int row = m0 + ma + mt * 16 + g;
            float2 v0, v1;
            v0.x = acc[mt][nt][0] * alpha + bv0;
            v0.y = acc[mt][nt][1] * alpha + bv1;
            v1.x = acc[mt][nt][2] * alpha + bv0;
            v1.y = acc[mt][nt][3] * alpha + bv1;
            *(float2*)(C + (long long)row * Ncols + col) = v0;
            *(float2*)(C + (long long)(row + 8) * Ncols + col) = v1;
        }
    }
}

// ---------------- softmax over the QUERY axis ----------------
__global__ void softmax_query_kernel(float* __restrict__ Sg)
{
    float* s = Sg + (long long)blockIdx.y * SEQ * SEQ;
    int m = blockIdx.x * blockDim.x + threadIdx.x;

    float mx = -1e30f;
    for (int n = 0; n < SEQ; n++) mx = fmaxf(mx, s[(long long)n * SEQ + m]);
    float sum = 0.f;
    for (int n = 0; n < SEQ; n++) {
        long long idx = (long long)n * SEQ + m;
        float e = __expf(s[idx] - mx);
        s[idx] = e;
        sum += e;
    }
    float inv = 1.f / sum;
    for (int n = 0; n < SEQ; n++) s[(long long)n * SEQ + m] *= inv;
}

// ---------------------------------------------------------------------------
extern "C" void kernel_launch(void* const* d_in, const int* in_sizes, int n_in,
                              void* d_out, int out_size)
{
    const float* x    = (const float*)d_in[0];   // [B,N,E]
    const float* Wq   = (const float*)d_in[1];   // [H,E,E]
    const float* Wk   = (const float*)d_in[2];
    const float* Wv   = (const float*)d_in[3];
    const float* fc_w = (const float*)d_in[4];   // [E,E]
    const float* fc_b = (const float*)d_in[5];   // [E]
    float* out = (float*)d_out;                  // [B,N,E]

    float *Q, *K, *V, *S, *Mn;
    cudaGetSymbolAddress((void**)&Q,  g_Q);
    cudaGetSymbolAddress((void**)&K,  g_K);
    cudaGetSymbolAddress((void**)&V,  g_V);
    cudaGetSymbolAddress((void**)&S,  g_S);
    cudaGetSymbolAddress((void**)&Mn, g_M);

    const int Mrows = BB * SEQ;                        // 8192
    const long long sW   = (long long)EE * EE;
    const long long sQKV = (long long)BB * SEQ * EE;

    // 1) Q/K/V[h] = X @ W[h]^T   (z = head)
    {
        dim3 grid(EE / 128, Mrows / 128, HH);
        gemm_mma<<<grid, 256>>>(x, Wq, Q, nullptr, Mrows, EE, EE, EE, 1.0f,
                                0, sW, sQKV, 1, 0, 0, 0);
        gemm_mma<<<grid, 256>>>(x, Wk, K, nullptr, Mrows, EE, EE, EE, 1.0f,
                                0, sW, sQKV, 1, 0, 0, 0);
        gemm_mma<<<grid, 256>>>(x, Wv, V, nullptr, Mrows, EE, EE, EE, 1.0f,
                                0, sW, sQKV, 1, 0, 0, 0);
    }

    // 2) S[hb] = Q[hb] @ K[hb]^T * scale   (z = h*B + b)
    {
        dim3 grid(SEQ / 128, SEQ / 128, HH * BB);
        const float scale = 1.0f / sqrtf((float)EE);
        gemm_mma<<<grid, 256>>>(Q, K, S, nullptr, SEQ, SEQ, EE, EE, scale,
                                (long long)SEQ * EE, (long long)SEQ * EE,
                                (long long)SEQ * SEQ, 1, 0, 0, 0);
    }

    // 3) softmax over the query axis (in-place)
    {
        dim3 grid(SEQ / 256, HH * BB);
        softmax_query_kernel<<<grid, 256>>>(S);
    }

    // 4) attn + mean over heads: C[b] = (1/3) * sum_h S[h,b] @ V[h,b]  (NN, z = b)
    {
        dim3 grid(EE / 128, SEQ / 128, BB);
        gemm_mma<<<grid, 256>>>(S, V, Mn, nullptr, SEQ, EE, SEQ, EE, 1.0f / 3.0f,
                                (long long)SEQ * SEQ, (long long)SEQ * EE,
                                (long long)SEQ * EE,
                                HH, (long long)BB * SEQ * SEQ, (long long)BB * SEQ * EE, 1);
    }

    // 5) out = Mn @ fc_w^T + fc_b
    {
        dim3 grid(EE / 128, Mrows / 128, 1);
        gemm_mma<<<grid, 256>>>(Mn, fc_w, out, fc_b, Mrows, EE, EE, EE, 1.0f,
                                0, 0, 0, 1, 0, 0, 0);
    }
}